// round 5
// baseline (speedup 1.0000x reference)
#include <cuda_runtime.h>
#include <cuda_fp16.h>
#include <mma.h>
#include <cstdint>

using namespace nvcuda;

#define N_NODES 100000
#define E_EDGES 1000000
#define IN_F    128
#define OUT_C   64      // NUM_HEADS * OUT_FEAT
#define NH      4
#define ALPHA   0.2f

// ---------------- scratch (static device arrays; no allocation) ----------------
__device__ __half g_Wh[(size_t)N_NODES * OUT_C];  // 12.8 MB fp16 messages
__device__ float  g_sa[(size_t)N_NODES * NH];     // s_src per node (fp32)
__device__ float  g_sb[(size_t)N_NODES * NH];     // s_dst per node (fp32)
__device__ int    g_cnt[N_NODES];                 // in-degree histogram
__device__ int    g_off[N_NODES];                 // CSR offsets (exclusive scan)
__device__ int    g_pos[N_NODES];                 // scatter cursors
__device__ int    g_srcs[E_EDGES];                // dst-grouped src list
__device__ int    g_is64;                         // edge_index dtype flag

// ---------------- dtype autodetect for edge_index ----------------
__global__ void detect_kernel(const void* ei)
{
    const long long* p = (const long long*)ei;
    int ok = 1;
    for (int i = 0; i < 256; i++) {
        long long v = p[i];
        if (v < 0 || v >= N_NODES) ok = 0;
    }
    g_is64 = ok;
}

// ---------------- GEMM: Wh = h @ W via split-fp16 3xHMMA, fused epilogue ------
#define GR   128
#define LDA  136
#define LDB  72
#define LDC  68

#define SM_AHI 0
#define SM_ALO (SM_AHI + GR * LDA * 2)
#define SM_BHI (SM_ALO + GR * LDA * 2)
#define SM_BLO (SM_BHI + IN_F * LDB * 2)
#define GEMM_SMEM_BYTES (SM_BLO + IN_F * LDB * 2) // 106496

__global__ __launch_bounds__(256)
void gemm_kernel(const float* __restrict__ h,
                 const float* __restrict__ W,
                 const float* __restrict__ a_src,
                 const float* __restrict__ a_dst)
{
    extern __shared__ char smem[];
    __half* Ahi = (__half*)(smem + SM_AHI);
    __half* Alo = (__half*)(smem + SM_ALO);
    __half* Bhi = (__half*)(smem + SM_BHI);
    __half* Blo = (__half*)(smem + SM_BLO);
    float*  Cs  = (float*)smem;                   // aliases A tiles after MMA

    const int tid  = threadIdx.x;
    const int wid  = tid >> 5;
    const int row0 = blockIdx.x * GR;

    // ---- stage A ----
    {
        const int row  = row0 + (tid >> 1);
        const int cbase = (tid & 1) * 64;
        __half* ahp = &Ahi[(tid >> 1) * LDA + cbase];
        __half* alp = &Alo[(tid >> 1) * LDA + cbase];
        if (row < N_NODES) {
            const float4* hp = (const float4*)(h + (size_t)row * IN_F + cbase);
            #pragma unroll
            for (int i = 0; i < 16; i++) {
                float4 v = hp[i];
                float vv[4] = {v.x, v.y, v.z, v.w};
                #pragma unroll
                for (int j = 0; j < 4; j++) {
                    __half hi = __float2half_rn(vv[j]);
                    __half lo = __float2half_rn(vv[j] - __half2float(hi));
                    ahp[i * 4 + j] = hi;
                    alp[i * 4 + j] = lo;
                }
            }
        } else {
            #pragma unroll
            for (int i = 0; i < 64; i++) { ahp[i] = __float2half_rn(0.f); alp[i] = __float2half_rn(0.f); }
        }
    }
    // ---- stage B ----
    {
        const float4* wp = (const float4*)(W + tid * 32);
        #pragma unroll
        for (int i = 0; i < 8; i++) {
            float4 v = wp[i];
            int idx = tid * 32 + i * 4;
            int k = idx >> 6, n = idx & 63;
            float vv[4] = {v.x, v.y, v.z, v.w};
            #pragma unroll
            for (int j = 0; j < 4; j++) {
                __half hi = __float2half_rn(vv[j]);
                __half lo = __float2half_rn(vv[j] - __half2float(hi));
                Bhi[k * LDB + n + j] = hi;
                Blo[k * LDB + n + j] = lo;
            }
        }
    }
    __syncthreads();

    wmma::fragment<wmma::accumulator, 16, 16, 16, float> acc[4];
    #pragma unroll
    for (int n = 0; n < 4; n++) wmma::fill_fragment(acc[n], 0.0f);

    #pragma unroll
    for (int k = 0; k < 8; k++) {
        wmma::fragment<wmma::matrix_a, 16, 16, 16, __half, wmma::row_major> ahi, alo;
        wmma::load_matrix_sync(ahi, &Ahi[(wid * 16) * LDA + k * 16], LDA);
        wmma::load_matrix_sync(alo, &Alo[(wid * 16) * LDA + k * 16], LDA);
        #pragma unroll
        for (int n = 0; n < 4; n++) {
            wmma::fragment<wmma::matrix_b, 16, 16, 16, __half, wmma::row_major> bhi, blo;
            wmma::load_matrix_sync(bhi, &Bhi[(k * 16) * LDB + n * 16], LDB);
            wmma::load_matrix_sync(blo, &Blo[(k * 16) * LDB + n * 16], LDB);
            wmma::mma_sync(acc[n], ahi, bhi, acc[n]);
            wmma::mma_sync(acc[n], ahi, blo, acc[n]);
            wmma::mma_sync(acc[n], alo, bhi, acc[n]);
        }
    }

    __syncthreads();
    #pragma unroll
    for (int n = 0; n < 4; n++)
        wmma::store_matrix_sync(&Cs[(wid * 16) * LDC + n * 16], acc[n], LDC, wmma::mem_row_major);
    __syncthreads();

    if (tid < GR) {
        const int row = row0 + tid;
        if (row < N_NODES) {
            const float* c = &Cs[tid * LDC];
            float sa[NH] = {0, 0, 0, 0}, sb[NH] = {0, 0, 0, 0};
            #pragma unroll
            for (int j = 0; j < OUT_C; j++) {
                const float v = c[j];
                const int hh = j >> 4;
                sa[hh] = fmaf(v, __ldg(&a_src[j]), sa[hh]);
                sb[hh] = fmaf(v, __ldg(&a_dst[j]), sb[hh]);
            }
            *(float4*)&g_sa[(size_t)row * NH] = make_float4(sa[0], sa[1], sa[2], sa[3]);
            *(float4*)&g_sb[(size_t)row * NH] = make_float4(sb[0], sb[1], sb[2], sb[3]);

            uint4* wout = (uint4*)&g_Wh[(size_t)row * OUT_C];
            #pragma unroll
            for (int q = 0; q < 8; q++) {
                uint4 u;
                ((__half2*)&u)[0] = __floats2half2_rn(c[q * 8 + 0], c[q * 8 + 1]);
                ((__half2*)&u)[1] = __floats2half2_rn(c[q * 8 + 2], c[q * 8 + 3]);
                ((__half2*)&u)[2] = __floats2half2_rn(c[q * 8 + 4], c[q * 8 + 5]);
                ((__half2*)&u)[3] = __floats2half2_rn(c[q * 8 + 6], c[q * 8 + 7]);
                wout[q] = u;
            }
        }
    }
}

// ---------------- CSR build: histogram -> scan -> scatter ----------------
__global__ __launch_bounds__(256)
void hist_kernel(const void* __restrict__ ei_raw)
{
    const int e = blockIdx.x * blockDim.x + threadIdx.x;
    if (e >= E_EDGES) return;
    int dst;
    if (g_is64) dst = (int)__ldg(&((const long long*)ei_raw)[(size_t)E_EDGES + e]);
    else        dst = __ldg(&((const int*)ei_raw)[(size_t)E_EDGES + e]);
    dst = min(max(dst, 0), N_NODES - 1);
    atomicAdd(&g_cnt[dst], 1);
}

__global__ __launch_bounds__(1024)
void scan_kernel()
{
    __shared__ int warp_sums[32];
    __shared__ int carry_s;
    const int tid = threadIdx.x;
    if (tid == 0) carry_s = 0;
    __syncthreads();

    for (int base = 0; base < N_NODES; base += 1024) {
        const int i = base + tid;
        const int v = (i < N_NODES) ? g_cnt[i] : 0;
        // inclusive warp scan
        int x = v;
        #pragma unroll
        for (int d = 1; d < 32; d <<= 1) {
            int y = __shfl_up_sync(0xffffffffu, x, d);
            if ((tid & 31) >= d) x += y;
        }
        if ((tid & 31) == 31) warp_sums[tid >> 5] = x;
        __syncthreads();
        if (tid < 32) {
            int s = warp_sums[tid];
            #pragma unroll
            for (int d = 1; d < 32; d <<= 1) {
                int y = __shfl_up_sync(0xffffffffu, s, d);
                if (tid >= d) s += y;
            }
            warp_sums[tid] = s;
        }
        __syncthreads();
        const int blockpref = (tid >= 32) ? warp_sums[(tid >> 5) - 1] : 0;
        const int incl = x + blockpref;
        const int carry = carry_s;
        if (i < N_NODES) {
            g_off[i] = carry + incl - v;
            g_pos[i] = carry + incl - v;
        }
        __syncthreads();
        if (tid == 1023) carry_s = carry + incl;
        __syncthreads();
    }
}

__global__ __launch_bounds__(256)
void scatter_kernel(const void* __restrict__ ei_raw)
{
    const int e = blockIdx.x * blockDim.x + threadIdx.x;
    if (e >= E_EDGES) return;
    int src, dst;
    if (g_is64) {
        src = (int)__ldg(&((const long long*)ei_raw)[e]);
        dst = (int)__ldg(&((const long long*)ei_raw)[(size_t)E_EDGES + e]);
    } else {
        src = __ldg(&((const int*)ei_raw)[e]);
        dst = __ldg(&((const int*)ei_raw)[(size_t)E_EDGES + e]);
    }
    src = min(max(src, 0), N_NODES - 1);
    dst = min(max(dst, 0), N_NODES - 1);
    const int pos = atomicAdd(&g_pos[dst], 1);
    g_srcs[pos] = src;
}

// ---------------- aggregate: one warp per dst node, no atomics ----------------
__global__ __launch_bounds__(256)
void aggregate_kernel(float* __restrict__ out)
{
    const int warp = (blockIdx.x * 256 + threadIdx.x) >> 5;
    const int lane = threadIdx.x & 31;
    if (warp >= N_NODES) return;
    const int n   = warp;
    const int off = g_off[n];
    const int deg = g_cnt[n];

    const int hh1 = lane & 3;   // phase-1 head
    const int g1  = lane >> 2;  // phase-1 edge-in-group
    const int hh2 = lane >> 3;  // phase-2 head for cols {2*lane, 2*lane+1}
    const float sb1 = g_sb[(size_t)n * NH + hh1];

    float acc0 = 0.0f, acc1 = 0.0f;

    for (int base = 0; base < deg; base += 8) {
        // phase 1: lanes (g1, hh1) compute attention for edges base..base+7
        const int eidx = off + min(base + g1, deg - 1);
        const int src1 = g_srcs[eidx];
        float e = g_sa[(size_t)src1 * NH + hh1] + sb1;
        e = (e >= 0.0f) ? e : ALPHA * e;
        float m = e;
        m = fmaxf(m, __shfl_xor_sync(0xffffffffu, m, 1));
        m = fmaxf(m, __shfl_xor_sync(0xffffffffu, m, 2));
        const float x = __expf(e - m);
        float s = x;
        s += __shfl_xor_sync(0xffffffffu, s, 1);
        s += __shfl_xor_sync(0xffffffffu, s, 2);
        const float att1 = x / s;

        // phase 2: accumulate the (up to) 8 edges
        #pragma unroll
        for (int g = 0; g < 8; g++) {
            if (base + g >= deg) break;     // uniform across warp
            const float a  = __shfl_sync(0xffffffffu, att1, (g << 2) | hh2);
            const int   sc = __shfl_sync(0xffffffffu, src1, g << 2);
            const unsigned wv = *(const unsigned*)&g_Wh[(size_t)sc * OUT_C + 2 * lane];
            const float2 f = __half22float2(*(const __half2*)&wv);
            acc0 = fmaf(a, f.x, acc0);
            acc1 = fmaf(a, f.y, acc1);
        }
    }

    // fused ReLU + single coalesced write (also covers degree-0 nodes with 0)
    *(float2*)&out[(size_t)n * OUT_C + 2 * lane] =
        make_float2(fmaxf(acc0, 0.0f), fmaxf(acc1, 0.0f));
}

// ---------------- launch ----------------
extern "C" void kernel_launch(void* const* d_in, const int* in_sizes, int n_in,
                              void* d_out, int out_size)
{
    const float* h     = nullptr;
    const void*  ei    = nullptr;
    const float* W     = nullptr;
    const float* a_src = nullptr;
    const float* a_dst = nullptr;
    for (int i = 0; i < n_in; i++) {
        const int s = in_sizes[i];
        if      (s == N_NODES * IN_F)  h  = (const float*)d_in[i];
        else if (s == 2 * E_EDGES)     ei = d_in[i];
        else if (s == IN_F * OUT_C)    W  = (const float*)d_in[i];
        else if (s == OUT_C) {
            if (!a_src) a_src = (const float*)d_in[i];
            else        a_dst = (const float*)d_in[i];
        }
    }
    if (!h || !ei || !W || !a_src || !a_dst) {
        h     = (const float*)d_in[0];
        ei    = d_in[1];
        W     = (const float*)d_in[2];
        a_src = (const float*)d_in[3];
        a_dst = (const float*)d_in[4];
    }
    float* out = (float*)d_out;

    detect_kernel<<<1, 1>>>(ei);

    // zero the degree histogram (400 KB)
    void* cnt_ptr = nullptr;
    cudaGetSymbolAddress(&cnt_ptr, g_cnt);
    cudaMemsetAsync(cnt_ptr, 0, N_NODES * sizeof(int), 0);

    cudaFuncSetAttribute(gemm_kernel,
                         cudaFuncAttributeMaxDynamicSharedMemorySize,
                         GEMM_SMEM_BYTES);
    gemm_kernel<<<(N_NODES + GR - 1) / GR, 256, GEMM_SMEM_BYTES>>>(h, W, a_src, a_dst);

    hist_kernel<<<(E_EDGES + 255) / 256, 256>>>(ei);
    scan_kernel<<<1, 1024>>>();
    scatter_kernel<<<(E_EDGES + 255) / 256, 256>>>(ei);

    const int nwarps_blocks = (N_NODES * 32 + 255) / 256;  // one warp per node
    aggregate_kernel<<<nwarps_blocks, 256>>>(out);
}

// round 8
// speedup vs baseline: 1.4745x; 1.4745x over previous
#include <cuda_runtime.h>
#include <cuda_fp16.h>
#include <mma.h>
#include <cstdint>

using namespace nvcuda;

#define N_NODES 100000
#define E_EDGES 1000000
#define IN_F    128
#define OUT_C   64      // NUM_HEADS * OUT_FEAT
#define NH      4
#define ALPHA   0.2f

#define SCAN_BLK 1024
#define NBLK     ((N_NODES + SCAN_BLK - 1) / SCAN_BLK)   // 98

// ---------------- scratch (static device arrays; no allocation) ----------------
__device__ __half g_Wh[(size_t)N_NODES * OUT_C];  // 12.8 MB fp16 messages
__device__ float  g_sa[(size_t)N_NODES * NH];     // s_src per node (fp32)
__device__ float  g_sb[(size_t)N_NODES * NH];     // s_dst per node (fp32)
__device__ int    g_cnt[N_NODES];                 // in-degree histogram
__device__ int    g_off[N_NODES];                 // CSR offsets (exclusive scan)
__device__ int    g_pos[N_NODES];                 // scatter cursors
__device__ int    g_srcs[E_EDGES];                // dst-grouped src list
__device__ int    g_part[NBLK];                   // scan block partials
__device__ int    g_is64;                         // edge_index dtype flag

// ---------------- dtype autodetect for edge_index ----------------
__global__ void detect_kernel(const void* ei)
{
    const long long* p = (const long long*)ei;
    int ok = 1;
    for (int i = 0; i < 256; i++) {
        long long v = p[i];
        if (v < 0 || v >= N_NODES) ok = 0;
    }
    g_is64 = ok;
}

// ---------------- GEMM: Wh = h @ W via split-fp16 3xHMMA, fused epilogue ------
#define GR   128
#define LDA  136
#define LDB  72
#define LDC  68

#define SM_AHI 0
#define SM_ALO (SM_AHI + GR * LDA * 2)
#define SM_BHI (SM_ALO + GR * LDA * 2)
#define SM_BLO (SM_BHI + IN_F * LDB * 2)
#define GEMM_SMEM_BYTES (SM_BLO + IN_F * LDB * 2) // 106496

__global__ __launch_bounds__(256)
void gemm_kernel(const float* __restrict__ h,
                 const float* __restrict__ W,
                 const float* __restrict__ a_src,
                 const float* __restrict__ a_dst)
{
    extern __shared__ char smem[];
    __half* Ahi = (__half*)(smem + SM_AHI);
    __half* Alo = (__half*)(smem + SM_ALO);
    __half* Bhi = (__half*)(smem + SM_BHI);
    __half* Blo = (__half*)(smem + SM_BLO);
    float*  Cs  = (float*)smem;                   // aliases A tiles after MMA

    const int tid  = threadIdx.x;
    const int wid  = tid >> 5;
    const int row0 = blockIdx.x * GR;

    // ---- stage A ----
    {
        const int row  = row0 + (tid >> 1);
        const int cbase = (tid & 1) * 64;
        __half* ahp = &Ahi[(tid >> 1) * LDA + cbase];
        __half* alp = &Alo[(tid >> 1) * LDA + cbase];
        if (row < N_NODES) {
            const float4* hp = (const float4*)(h + (size_t)row * IN_F + cbase);
            #pragma unroll
            for (int i = 0; i < 16; i++) {
                float4 v = hp[i];
                float vv[4] = {v.x, v.y, v.z, v.w};
                #pragma unroll
                for (int j = 0; j < 4; j++) {
                    __half hi = __float2half_rn(vv[j]);
                    __half lo = __float2half_rn(vv[j] - __half2float(hi));
                    ahp[i * 4 + j] = hi;
                    alp[i * 4 + j] = lo;
                }
            }
        } else {
            #pragma unroll
            for (int i = 0; i < 64; i++) { ahp[i] = __float2half_rn(0.f); alp[i] = __float2half_rn(0.f); }
        }
    }
    // ---- stage B ----
    {
        const float4* wp = (const float4*)(W + tid * 32);
        #pragma unroll
        for (int i = 0; i < 8; i++) {
            float4 v = wp[i];
            int idx = tid * 32 + i * 4;
            int k = idx >> 6, n = idx & 63;
            float vv[4] = {v.x, v.y, v.z, v.w};
            #pragma unroll
            for (int j = 0; j < 4; j++) {
                __half hi = __float2half_rn(vv[j]);
                __half lo = __float2half_rn(vv[j] - __half2float(hi));
                Bhi[k * LDB + n + j] = hi;
                Blo[k * LDB + n + j] = lo;
            }
        }
    }
    __syncthreads();

    wmma::fragment<wmma::accumulator, 16, 16, 16, float> acc[4];
    #pragma unroll
    for (int n = 0; n < 4; n++) wmma::fill_fragment(acc[n], 0.0f);

    #pragma unroll
    for (int k = 0; k < 8; k++) {
        wmma::fragment<wmma::matrix_a, 16, 16, 16, __half, wmma::row_major> ahi, alo;
        wmma::load_matrix_sync(ahi, &Ahi[(wid * 16) * LDA + k * 16], LDA);
        wmma::load_matrix_sync(alo, &Alo[(wid * 16) * LDA + k * 16], LDA);
        #pragma unroll
        for (int n = 0; n < 4; n++) {
            wmma::fragment<wmma::matrix_b, 16, 16, 16, __half, wmma::row_major> bhi, blo;
            wmma::load_matrix_sync(bhi, &Bhi[(k * 16) * LDB + n * 16], LDB);
            wmma::load_matrix_sync(blo, &Blo[(k * 16) * LDB + n * 16], LDB);
            wmma::mma_sync(acc[n], ahi, bhi, acc[n]);
            wmma::mma_sync(acc[n], ahi, blo, acc[n]);
            wmma::mma_sync(acc[n], alo, bhi, acc[n]);
        }
    }

    __syncthreads();
    #pragma unroll
    for (int n = 0; n < 4; n++)
        wmma::store_matrix_sync(&Cs[(wid * 16) * LDC + n * 16], acc[n], LDC, wmma::mem_row_major);
    __syncthreads();

    if (tid < GR) {
        const int row = row0 + tid;
        if (row < N_NODES) {
            const float* c = &Cs[tid * LDC];
            float sa[NH] = {0, 0, 0, 0}, sb[NH] = {0, 0, 0, 0};
            #pragma unroll
            for (int j = 0; j < OUT_C; j++) {
                const float v = c[j];
                const int hh = j >> 4;
                sa[hh] = fmaf(v, __ldg(&a_src[j]), sa[hh]);
                sb[hh] = fmaf(v, __ldg(&a_dst[j]), sb[hh]);
            }
            *(float4*)&g_sa[(size_t)row * NH] = make_float4(sa[0], sa[1], sa[2], sa[3]);
            *(float4*)&g_sb[(size_t)row * NH] = make_float4(sb[0], sb[1], sb[2], sb[3]);

            uint4* wout = (uint4*)&g_Wh[(size_t)row * OUT_C];
            #pragma unroll
            for (int q = 0; q < 8; q++) {
                uint4 u;
                ((__half2*)&u)[0] = __floats2half2_rn(c[q * 8 + 0], c[q * 8 + 1]);
                ((__half2*)&u)[1] = __floats2half2_rn(c[q * 8 + 2], c[q * 8 + 3]);
                ((__half2*)&u)[2] = __floats2half2_rn(c[q * 8 + 4], c[q * 8 + 5]);
                ((__half2*)&u)[3] = __floats2half2_rn(c[q * 8 + 6], c[q * 8 + 7]);
                wout[q] = u;
            }
        }
    }
}

// ---------------- CSR build: histogram -> 3-kernel scan -> scatter ------------
__global__ __launch_bounds__(256)
void hist_kernel(const void* __restrict__ ei_raw)
{
    const int e = blockIdx.x * blockDim.x + threadIdx.x;
    if (e >= E_EDGES) return;
    int dst;
    if (g_is64) dst = (int)__ldg(&((const long long*)ei_raw)[(size_t)E_EDGES + e]);
    else        dst = __ldg(&((const int*)ei_raw)[(size_t)E_EDGES + e]);
    dst = min(max(dst, 0), N_NODES - 1);
    atomicAdd(&g_cnt[dst], 1);
}

// pass 1: per-block sums of g_cnt
__global__ __launch_bounds__(SCAN_BLK)
void scan_reduce()
{
    __shared__ int wsum[32];
    const int tid = threadIdx.x;
    const int i   = blockIdx.x * SCAN_BLK + tid;
    int v = (i < N_NODES) ? g_cnt[i] : 0;
    #pragma unroll
    for (int d = 16; d > 0; d >>= 1) v += __shfl_xor_sync(0xffffffffu, v, d);
    if ((tid & 31) == 0) wsum[tid >> 5] = v;
    __syncthreads();
    if (tid < 32) {
        int s = wsum[tid];
        #pragma unroll
        for (int d = 16; d > 0; d >>= 1) s += __shfl_xor_sync(0xffffffffu, s, d);
        if (tid == 0) g_part[blockIdx.x] = s;
    }
}

// pass 2: exclusive scan of NBLK (=98) partials in one block
__global__ __launch_bounds__(128)
void scan_part()
{
    __shared__ int wsum[4];
    const int tid = threadIdx.x;
    const int v = (tid < NBLK) ? g_part[tid] : 0;
    int x = v;
    #pragma unroll
    for (int d = 1; d < 32; d <<= 1) {
        int y = __shfl_up_sync(0xffffffffu, x, d);
        if ((tid & 31) >= d) x += y;
    }
    if ((tid & 31) == 31) wsum[tid >> 5] = x;
    __syncthreads();
    int pre = 0;
    #pragma unroll
    for (int w = 0; w < 4; w++) pre += (w < (tid >> 5)) ? wsum[w] : 0;
    if (tid < NBLK) g_part[tid] = pre + x - v;   // exclusive
}

// pass 3: block-local exclusive scan + block offset -> g_off / g_pos
__global__ __launch_bounds__(SCAN_BLK)
void scan_final()
{
    __shared__ int wsum[32];
    const int tid = threadIdx.x;
    const int i   = blockIdx.x * SCAN_BLK + tid;
    const int v = (i < N_NODES) ? g_cnt[i] : 0;
    int x = v;
    #pragma unroll
    for (int d = 1; d < 32; d <<= 1) {
        int y = __shfl_up_sync(0xffffffffu, x, d);
        if ((tid & 31) >= d) x += y;
    }
    if ((tid & 31) == 31) wsum[tid >> 5] = x;
    __syncthreads();
    if (tid < 32) {
        int s = wsum[tid];
        #pragma unroll
        for (int d = 1; d < 32; d <<= 1) {
            int y = __shfl_up_sync(0xffffffffu, s, d);
            if (tid >= d) s += y;
        }
        wsum[tid] = s;
    }
    __syncthreads();
    const int blockpref = (tid >= 32) ? wsum[(tid >> 5) - 1] : 0;
    if (i < N_NODES) {
        const int off = g_part[blockIdx.x] + blockpref + x - v;
        g_off[i] = off;
        g_pos[i] = off;
    }
}

__global__ __launch_bounds__(256)
void scatter_kernel(const void* __restrict__ ei_raw)
{
    const int e = blockIdx.x * blockDim.x + threadIdx.x;
    if (e >= E_EDGES) return;
    int src, dst;
    if (g_is64) {
        src = (int)__ldg(&((const long long*)ei_raw)[e]);
        dst = (int)__ldg(&((const long long*)ei_raw)[(size_t)E_EDGES + e]);
    } else {
        src = __ldg(&((const int*)ei_raw)[e]);
        dst = __ldg(&((const int*)ei_raw)[(size_t)E_EDGES + e]);
    }
    src = min(max(src, 0), N_NODES - 1);
    dst = min(max(dst, 0), N_NODES - 1);
    const int pos = atomicAdd(&g_pos[dst], 1);
    g_srcs[pos] = src;
}

// ---------------- aggregate: one warp per dst node, no atomics ----------------
__global__ __launch_bounds__(256)
void aggregate_kernel(float* __restrict__ out)
{
    const int warp = (blockIdx.x * 256 + threadIdx.x) >> 5;
    const int lane = threadIdx.x & 31;
    if (warp >= N_NODES) return;
    const int n   = warp;
    const int off = g_off[n];
    const int deg = g_cnt[n];

    const int hh1 = lane & 3;   // phase-1 head
    const int g1  = lane >> 2;  // phase-1 edge-in-group
    const int hh2 = lane >> 3;  // phase-2 head for cols {2*lane, 2*lane+1}
    const float sb1 = g_sb[(size_t)n * NH + hh1];

    float acc0 = 0.0f, acc1 = 0.0f;

    for (int base = 0; base < deg; base += 8) {
        const int cnt = min(8, deg - base);   // uniform across warp

        // phase 1: lanes (g1, hh1) compute attention for edges base..base+cnt-1
        const int eidx = off + base + ((g1 < cnt) ? g1 : cnt - 1);
        const int src1 = g_srcs[eidx];
        float e = g_sa[(size_t)src1 * NH + hh1] + sb1;
        e = (e >= 0.0f) ? e : ALPHA * e;
        float m = e;
        m = fmaxf(m, __shfl_xor_sync(0xffffffffu, m, 1));
        m = fmaxf(m, __shfl_xor_sync(0xffffffffu, m, 2));
        const float x = __expf(e - m);
        float s = x;
        s += __shfl_xor_sync(0xffffffffu, s, 1);
        s += __shfl_xor_sync(0xffffffffu, s, 2);
        const float att1 = x / s;

        // phase 2: accumulate the cnt edges
        #pragma unroll
        for (int g = 0; g < 8; g++) {
            if (g >= cnt) break;             // uniform across warp
            const float a  = __shfl_sync(0xffffffffu, att1, (g << 2) | hh2);
            const int   sc = __shfl_sync(0xffffffffu, src1, g << 2);
            const unsigned wv = *(const unsigned*)&g_Wh[(size_t)sc * OUT_C + 2 * lane];
            const float2 f = __half22float2(*(const __half2*)&wv);
            acc0 = fmaf(a, f.x, acc0);
            acc1 = fmaf(a, f.y, acc1);
        }
    }

    // fused ReLU + single coalesced write (also covers degree-0 nodes with 0)
    *(float2*)&out[(size_t)n * OUT_C + 2 * lane] =
        make_float2(fmaxf(acc0, 0.0f), fmaxf(acc1, 0.0f));
}

// ---------------- launch ----------------
extern "C" void kernel_launch(void* const* d_in, const int* in_sizes, int n_in,
                              void* d_out, int out_size)
{
    const float* h     = nullptr;
    const void*  ei    = nullptr;
    const float* W     = nullptr;
    const float* a_src = nullptr;
    const float* a_dst = nullptr;
    for (int i = 0; i < n_in; i++) {
        const int s = in_sizes[i];
        if      (s == N_NODES * IN_F)  h  = (const float*)d_in[i];
        else if (s == 2 * E_EDGES)     ei = d_in[i];
        else if (s == IN_F * OUT_C)    W  = (const float*)d_in[i];
        else if (s == OUT_C) {
            if (!a_src) a_src = (const float*)d_in[i];
            else        a_dst = (const float*)d_in[i];
        }
    }
    if (!h || !ei || !W || !a_src || !a_dst) {
        h     = (const float*)d_in[0];
        ei    = d_in[1];
        W     = (const float*)d_in[2];
        a_src = (const float*)d_in[3];
        a_dst = (const float*)d_in[4];
    }
    float* out = (float*)d_out;

    detect_kernel<<<1, 1>>>(ei);

    void* cnt_ptr = nullptr;
    cudaGetSymbolAddress(&cnt_ptr, g_cnt);
    cudaMemsetAsync(cnt_ptr, 0, N_NODES * sizeof(int), 0);

    cudaFuncSetAttribute(gemm_kernel,
                         cudaFuncAttributeMaxDynamicSharedMemorySize,
                         GEMM_SMEM_BYTES);
    gemm_kernel<<<(N_NODES + GR - 1) / GR, 256, GEMM_SMEM_BYTES>>>(h, W, a_src, a_dst);

    hist_kernel<<<(E_EDGES + 255) / 256, 256>>>(ei);
    scan_reduce<<<NBLK, SCAN_BLK>>>();
    scan_part<<<1, 128>>>();
    scan_final<<<NBLK, SCAN_BLK>>>();
    scatter_kernel<<<(E_EDGES + 255) / 256, 256>>>(ei);

    const int nwarps_blocks = (N_NODES * 32 + 255) / 256;  // one warp per node
    aggregate_kernel<<<nwarps_blocks, 256>>>(out);
}

// round 11
// speedup vs baseline: 1.4959x; 1.0146x over previous
#include <cuda_runtime.h>
#include <cuda_fp16.h>
#include <mma.h>
#include <cstdint>

using namespace nvcuda;

#define N_NODES 100000
#define E_EDGES 1000000
#define IN_F    128
#define OUT_C   64      // NUM_HEADS * OUT_FEAT
#define NH      4
#define ALPHA   0.2f

#define SCAN_BLK 1024
#define NBLK     ((N_NODES + SCAN_BLK - 1) / SCAN_BLK)   // 98

// ---------------- scratch (static device arrays; no allocation) ----------------
__device__ __half g_Wh[(size_t)N_NODES * OUT_C];  // 12.8 MB fp16 messages
__device__ float  g_sa[(size_t)N_NODES * NH];     // s_src per node (fp32)
__device__ float  g_sb[(size_t)N_NODES * NH];     // s_dst per node (fp32)
__device__ int    g_cnt[N_NODES];                 // in-degree histogram
__device__ int    g_off[N_NODES];                 // CSR offsets (exclusive scan)
__device__ int    g_pos[N_NODES];                 // scatter cursors
__device__ int    g_srcs[E_EDGES];                // dst-grouped src list
__device__ int    g_part[NBLK];                   // scan block partials
__device__ int    g_is64;                         // edge_index dtype flag

// ---------------- dtype autodetect for edge_index ----------------
__global__ void detect_kernel(const void* ei)
{
    const long long* p = (const long long*)ei;
    int ok = 1;
    for (int i = 0; i < 256; i++) {
        long long v = p[i];
        if (v < 0 || v >= N_NODES) ok = 0;
    }
    g_is64 = ok;
}

// ---------------- GEMM: Wh = h @ W via split-fp16 3xHMMA, fused epilogue ------
#define GR   128
#define LDA  136
#define LDB  72
#define LDC  68

#define SM_AHI 0
#define SM_ALO (SM_AHI + GR * LDA * 2)
#define SM_BHI (SM_ALO + GR * LDA * 2)
#define SM_BLO (SM_BHI + IN_F * LDB * 2)
#define GEMM_SMEM_BYTES (SM_BLO + IN_F * LDB * 2) // 106496

__global__ __launch_bounds__(256)
void gemm_kernel(const float* __restrict__ h,
                 const float* __restrict__ W,
                 const float* __restrict__ a_src,
                 const float* __restrict__ a_dst)
{
    extern __shared__ char smem[];
    __half* Ahi = (__half*)(smem + SM_AHI);
    __half* Alo = (__half*)(smem + SM_ALO);
    __half* Bhi = (__half*)(smem + SM_BHI);
    __half* Blo = (__half*)(smem + SM_BLO);
    float*  Cs  = (float*)smem;                   // aliases A tiles after MMA

    const int tid  = threadIdx.x;
    const int wid  = tid >> 5;
    const int row0 = blockIdx.x * GR;

    // ---- stage A ----
    {
        const int row  = row0 + (tid >> 1);
        const int cbase = (tid & 1) * 64;
        __half* ahp = &Ahi[(tid >> 1) * LDA + cbase];
        __half* alp = &Alo[(tid >> 1) * LDA + cbase];
        if (row < N_NODES) {
            const float4* hp = (const float4*)(h + (size_t)row * IN_F + cbase);
            #pragma unroll
            for (int i = 0; i < 16; i++) {
                float4 v = hp[i];
                float vv[4] = {v.x, v.y, v.z, v.w};
                #pragma unroll
                for (int j = 0; j < 4; j++) {
                    __half hi = __float2half_rn(vv[j]);
                    __half lo = __float2half_rn(vv[j] - __half2float(hi));
                    ahp[i * 4 + j] = hi;
                    alp[i * 4 + j] = lo;
                }
            }
        } else {
            #pragma unroll
            for (int i = 0; i < 64; i++) { ahp[i] = __float2half_rn(0.f); alp[i] = __float2half_rn(0.f); }
        }
    }
    // ---- stage B ----
    {
        const float4* wp = (const float4*)(W + tid * 32);
        #pragma unroll
        for (int i = 0; i < 8; i++) {
            float4 v = wp[i];
            int idx = tid * 32 + i * 4;
            int k = idx >> 6, n = idx & 63;
            float vv[4] = {v.x, v.y, v.z, v.w};
            #pragma unroll
            for (int j = 0; j < 4; j++) {
                __half hi = __float2half_rn(vv[j]);
                __half lo = __float2half_rn(vv[j] - __half2float(hi));
                Bhi[k * LDB + n + j] = hi;
                Blo[k * LDB + n + j] = lo;
            }
        }
    }
    __syncthreads();

    wmma::fragment<wmma::accumulator, 16, 16, 16, float> acc[4];
    #pragma unroll
    for (int n = 0; n < 4; n++) wmma::fill_fragment(acc[n], 0.0f);

    #pragma unroll
    for (int k = 0; k < 8; k++) {
        wmma::fragment<wmma::matrix_a, 16, 16, 16, __half, wmma::row_major> ahi, alo;
        wmma::load_matrix_sync(ahi, &Ahi[(wid * 16) * LDA + k * 16], LDA);
        wmma::load_matrix_sync(alo, &Alo[(wid * 16) * LDA + k * 16], LDA);
        #pragma unroll
        for (int n = 0; n < 4; n++) {
            wmma::fragment<wmma::matrix_b, 16, 16, 16, __half, wmma::row_major> bhi, blo;
            wmma::load_matrix_sync(bhi, &Bhi[(k * 16) * LDB + n * 16], LDB);
            wmma::load_matrix_sync(blo, &Blo[(k * 16) * LDB + n * 16], LDB);
            wmma::mma_sync(acc[n], ahi, bhi, acc[n]);
            wmma::mma_sync(acc[n], ahi, blo, acc[n]);
            wmma::mma_sync(acc[n], alo, bhi, acc[n]);
        }
    }

    __syncthreads();
    #pragma unroll
    for (int n = 0; n < 4; n++)
        wmma::store_matrix_sync(&Cs[(wid * 16) * LDC + n * 16], acc[n], LDC, wmma::mem_row_major);
    __syncthreads();

    if (tid < GR) {
        const int row = row0 + tid;
        if (row < N_NODES) {
            const float* c = &Cs[tid * LDC];
            float sa[NH] = {0, 0, 0, 0}, sb[NH] = {0, 0, 0, 0};
            #pragma unroll
            for (int j = 0; j < OUT_C; j++) {
                const float v = c[j];
                const int hh = j >> 4;
                sa[hh] = fmaf(v, __ldg(&a_src[j]), sa[hh]);
                sb[hh] = fmaf(v, __ldg(&a_dst[j]), sb[hh]);
            }
            *(float4*)&g_sa[(size_t)row * NH] = make_float4(sa[0], sa[1], sa[2], sa[3]);
            *(float4*)&g_sb[(size_t)row * NH] = make_float4(sb[0], sb[1], sb[2], sb[3]);

            uint4* wout = (uint4*)&g_Wh[(size_t)row * OUT_C];
            #pragma unroll
            for (int q = 0; q < 8; q++) {
                uint4 u;
                ((__half2*)&u)[0] = __floats2half2_rn(c[q * 8 + 0], c[q * 8 + 1]);
                ((__half2*)&u)[1] = __floats2half2_rn(c[q * 8 + 2], c[q * 8 + 3]);
                ((__half2*)&u)[2] = __floats2half2_rn(c[q * 8 + 4], c[q * 8 + 5]);
                ((__half2*)&u)[3] = __floats2half2_rn(c[q * 8 + 6], c[q * 8 + 7]);
                wout[q] = u;
            }
        }
    }
}

// ---------------- CSR build: histogram -> 3-kernel scan -> scatter ------------
__global__ __launch_bounds__(256)
void hist_kernel(const void* __restrict__ ei_raw)
{
    const int e = blockIdx.x * blockDim.x + threadIdx.x;
    if (e >= E_EDGES) return;
    int dst;
    if (g_is64) dst = (int)__ldg(&((const long long*)ei_raw)[(size_t)E_EDGES + e]);
    else        dst = __ldg(&((const int*)ei_raw)[(size_t)E_EDGES + e]);
    dst = min(max(dst, 0), N_NODES - 1);
    atomicAdd(&g_cnt[dst], 1);
}

// pass 1: per-block sums of g_cnt
__global__ __launch_bounds__(SCAN_BLK)
void scan_reduce()
{
    __shared__ int wsum[32];
    const int tid = threadIdx.x;
    const int i   = blockIdx.x * SCAN_BLK + tid;
    int v = (i < N_NODES) ? g_cnt[i] : 0;
    #pragma unroll
    for (int d = 16; d > 0; d >>= 1) v += __shfl_xor_sync(0xffffffffu, v, d);
    if ((tid & 31) == 0) wsum[tid >> 5] = v;
    __syncthreads();
    if (tid < 32) {
        int s = wsum[tid];
        #pragma unroll
        for (int d = 16; d > 0; d >>= 1) s += __shfl_xor_sync(0xffffffffu, s, d);
        if (tid == 0) g_part[blockIdx.x] = s;
    }
}

// pass 2: exclusive scan of NBLK (=98) partials in one block
__global__ __launch_bounds__(128)
void scan_part()
{
    __shared__ int wsum[4];
    const int tid = threadIdx.x;
    const int v = (tid < NBLK) ? g_part[tid] : 0;
    int x = v;
    #pragma unroll
    for (int d = 1; d < 32; d <<= 1) {
        int y = __shfl_up_sync(0xffffffffu, x, d);
        if ((tid & 31) >= d) x += y;
    }
    if ((tid & 31) == 31) wsum[tid >> 5] = x;
    __syncthreads();
    int pre = 0;
    #pragma unroll
    for (int w = 0; w < 4; w++) pre += (w < (tid >> 5)) ? wsum[w] : 0;
    if (tid < NBLK) g_part[tid] = pre + x - v;   // exclusive
}

// pass 3: block-local exclusive scan + block offset -> g_off / g_pos
__global__ __launch_bounds__(SCAN_BLK)
void scan_final()
{
    __shared__ int wsum[32];
    const int tid = threadIdx.x;
    const int i   = blockIdx.x * SCAN_BLK + tid;
    const int v = (i < N_NODES) ? g_cnt[i] : 0;
    int x = v;
    #pragma unroll
    for (int d = 1; d < 32; d <<= 1) {
        int y = __shfl_up_sync(0xffffffffu, x, d);
        if ((tid & 31) >= d) x += y;
    }
    if ((tid & 31) == 31) wsum[tid >> 5] = x;
    __syncthreads();
    if (tid < 32) {
        int s = wsum[tid];
        #pragma unroll
        for (int d = 1; d < 32; d <<= 1) {
            int y = __shfl_up_sync(0xffffffffu, s, d);
            if (tid >= d) s += y;
        }
        wsum[tid] = s;
    }
    __syncthreads();
    const int blockpref = (tid >= 32) ? wsum[(tid >> 5) - 1] : 0;
    if (i < N_NODES) {
        const int off = g_part[blockIdx.x] + blockpref + x - v;
        g_off[i] = off;
        g_pos[i] = off;
    }
}

__global__ __launch_bounds__(256)
void scatter_kernel(const void* __restrict__ ei_raw)
{
    const int e = blockIdx.x * blockDim.x + threadIdx.x;
    if (e >= E_EDGES) return;
    int src, dst;
    if (g_is64) {
        src = (int)__ldg(&((const long long*)ei_raw)[e]);
        dst = (int)__ldg(&((const long long*)ei_raw)[(size_t)E_EDGES + e]);
    } else {
        src = __ldg(&((const int*)ei_raw)[e]);
        dst = __ldg(&((const int*)ei_raw)[(size_t)E_EDGES + e]);
    }
    src = min(max(src, 0), N_NODES - 1);
    dst = min(max(dst, 0), N_NODES - 1);
    const int pos = atomicAdd(&g_pos[dst], 1);
    g_srcs[pos] = src;
}

// ---------------- aggregate: one warp per dst node, branchless MLP-8 ----------
__global__ __launch_bounds__(256)
void aggregate_kernel(float* __restrict__ out)
{
    const int warp = (blockIdx.x * 256 + threadIdx.x) >> 5;
    const int lane = threadIdx.x & 31;
    if (warp >= N_NODES) return;
    const int n   = warp;
    const int off = g_off[n];
    const int deg = g_cnt[n];

    const int hh1 = lane & 3;   // phase-1 head
    const int g1  = lane >> 2;  // phase-1 edge-in-group
    const int hh2 = lane >> 3;  // phase-2 head for cols {2*lane, 2*lane+1}
    const float sb1 = g_sb[(size_t)n * NH + hh1];

    float acc0 = 0.0f, acc1 = 0.0f;

    for (int base = 0; base < deg; base += 8) {
        const int cnt = min(8, deg - base);   // uniform across warp

        // phase 1: lanes (g1, hh1) compute attention for edges base..base+cnt-1
        // (padded lanes replicate the last valid edge; their weight is zeroed below)
        const int eidx = off + base + ((g1 < cnt) ? g1 : cnt - 1);
        const int src1 = g_srcs[eidx];
        float e = g_sa[(size_t)src1 * NH + hh1] + sb1;
        e = (e >= 0.0f) ? e : ALPHA * e;
        float m = e;
        m = fmaxf(m, __shfl_xor_sync(0xffffffffu, m, 1));
        m = fmaxf(m, __shfl_xor_sync(0xffffffffu, m, 2));
        const float x = __expf(e - m);
        float s = x;
        s += __shfl_xor_sync(0xffffffffu, s, 1);
        s += __shfl_xor_sync(0xffffffffu, s, 2);
        const float att1 = x / s;

        // phase 2a: batch ALL 8 gathers (branchless -> 8 loads in flight)
        float    av[8];
        unsigned wv[8];
        #pragma unroll
        for (int g = 0; g < 8; g++) {
            av[g] = __shfl_sync(0xffffffffu, att1, (g << 2) | hh2);
            const int sc = __shfl_sync(0xffffffffu, src1, g << 2);
            wv[g] = *(const unsigned*)&g_Wh[(size_t)sc * OUT_C + 2 * lane];
        }
        // phase 2b: FMA with zero weight for padded slots (exact: a*0 contributes 0)
        #pragma unroll
        for (int g = 0; g < 8; g++) {
            const float a = (g < cnt) ? av[g] : 0.0f;
            const float2 f = __half22float2(*(const __half2*)&wv[g]);
            acc0 = fmaf(a, f.x, acc0);
            acc1 = fmaf(a, f.y, acc1);
        }
    }

    // fused ReLU + single coalesced write (also covers degree-0 nodes with 0)
    *(float2*)&out[(size_t)n * OUT_C + 2 * lane] =
        make_float2(fmaxf(acc0, 0.0f), fmaxf(acc1, 0.0f));
}

// ---------------- launch ----------------
extern "C" void kernel_launch(void* const* d_in, const int* in_sizes, int n_in,
                              void* d_out, int out_size)
{
    const float* h     = nullptr;
    const void*  ei    = nullptr;
    const float* W     = nullptr;
    const float* a_src = nullptr;
    const float* a_dst = nullptr;
    for (int i = 0; i < n_in; i++) {
        const int s = in_sizes[i];
        if      (s == N_NODES * IN_F)  h  = (const float*)d_in[i];
        else if (s == 2 * E_EDGES)     ei = d_in[i];
        else if (s == IN_F * OUT_C)    W  = (const float*)d_in[i];
        else if (s == OUT_C) {
            if (!a_src) a_src = (const float*)d_in[i];
            else        a_dst = (const float*)d_in[i];
        }
    }
    if (!h || !ei || !W || !a_src || !a_dst) {
        h     = (const float*)d_in[0];
        ei    = d_in[1];
        W     = (const float*)d_in[2];
        a_src = (const float*)d_in[3];
        a_dst = (const float*)d_in[4];
    }
    float* out = (float*)d_out;

    detect_kernel<<<1, 1>>>(ei);

    void* cnt_ptr = nullptr;
    cudaGetSymbolAddress(&cnt_ptr, g_cnt);
    cudaMemsetAsync(cnt_ptr, 0, N_NODES * sizeof(int), 0);

    cudaFuncSetAttribute(gemm_kernel,
                         cudaFuncAttributeMaxDynamicSharedMemorySize,
                         GEMM_SMEM_BYTES);
    gemm_kernel<<<(N_NODES + GR - 1) / GR, 256, GEMM_SMEM_BYTES>>>(h, W, a_src, a_dst);

    hist_kernel<<<(E_EDGES + 255) / 256, 256>>>(ei);
    scan_reduce<<<NBLK, SCAN_BLK>>>();
    scan_part<<<1, 128>>>();
    scan_final<<<NBLK, SCAN_BLK>>>();
    scatter_kernel<<<(E_EDGES + 255) / 256, 256>>>(ei);

    const int nwarps_blocks = (N_NODES * 32 + 255) / 256;  // one warp per node
    aggregate_kernel<<<nwarps_blocks, 256>>>(out);
}

// round 14
// speedup vs baseline: 1.8144x; 1.2129x over previous
#include <cuda_runtime.h>
#include <cuda_fp16.h>
#include <mma.h>
#include <cstdint>

using namespace nvcuda;

#define N_NODES 100000
#define E_EDGES 1000000
#define IN_F    128
#define OUT_C   64      // NUM_HEADS * OUT_FEAT
#define NH      4
#define ALPHA   0.2f

#define BT      1024
#define NBLK    ((N_NODES + BT - 1) / BT)   // 98 blocks (co-resident on 148 SMs)

// ---------------- scratch (static device arrays; no allocation) ----------------
__device__ __half g_Wh[(size_t)N_NODES * OUT_C];  // 12.8 MB fp16 messages
__device__ float  g_sa[(size_t)N_NODES * NH];     // s_src per node (fp32)
__device__ float  g_sb[(size_t)N_NODES * NH];     // s_dst per node (fp32)
__device__ int    g_cnt[N_NODES];                 // in-degree histogram
__device__ int    g_off[N_NODES];                 // CSR offsets (exclusive scan)
__device__ int    g_pos[N_NODES];                 // scatter cursors
__device__ int    g_srcs[E_EDGES];                // dst-grouped src list
__device__ int    g_part[NBLK];                   // scan block partials
__device__ int    g_is64;                         // edge_index dtype flag
__device__ unsigned g_bars[8];                    // generation-ticket barrier counters

__device__ __forceinline__ unsigned h2u(__half2 h) { return *(unsigned*)&h; }

// Generation-ticket grid barrier: reusable with NO reset, safe under tool-driven
// kernel replays (ncu multi-pass). Blocks co-resident: 98 blocks <= 148 SMs.
__device__ __forceinline__ void grid_bar(int idx, unsigned nb)
{
    __threadfence();
    __syncthreads();
    if (threadIdx.x == 0) {
        const unsigned ticket = atomicAdd(&g_bars[idx], 1u);
        const unsigned target = (ticket / nb + 1u) * nb;
        while (*(volatile unsigned*)&g_bars[idx] < target) { }
        __threadfence();
    }
    __syncthreads();
}

// ---------------- GEMM: Wh = h @ W via split-fp16 3xHMMA, fused epilogue ------
#define GR   128
#define LDA  136
#define LDB  72
#define LDC  68

#define SM_AHI 0
#define SM_ALO (SM_AHI + GR * LDA * 2)
#define SM_BHI (SM_ALO + GR * LDA * 2)
#define SM_BLO (SM_BHI + IN_F * LDB * 2)
#define GEMM_SMEM_BYTES (SM_BLO + IN_F * LDB * 2) // 106496

__global__ __launch_bounds__(256)
void gemm_kernel(const float* __restrict__ h,
                 const float* __restrict__ W,
                 const float* __restrict__ a_src,
                 const float* __restrict__ a_dst)
{
    extern __shared__ char smem[];
    __half* Ahi = (__half*)(smem + SM_AHI);
    __half* Alo = (__half*)(smem + SM_ALO);
    __half* Bhi = (__half*)(smem + SM_BHI);
    __half* Blo = (__half*)(smem + SM_BLO);
    float*  Cs  = (float*)smem;                   // aliases A tiles after MMA

    const int tid  = threadIdx.x;
    const int wid  = tid >> 5;
    const int row0 = blockIdx.x * GR;

    // ---- stage A (coalesced: warp reads contiguous 512B, packed uint2 STS) ----
    #pragma unroll
    for (int i = 0; i < 16; i++) {
        const int f   = i * 256 + tid;   // float4 index in 128x128 tile
        const int row = f >> 5;          // 32 float4 per row
        const int c4  = f & 31;
        float4 v = make_float4(0.f, 0.f, 0.f, 0.f);
        if (row0 + row < N_NODES)
            v = *(const float4*)(h + (size_t)(row0 + row) * IN_F + c4 * 4);
        __half2 h01 = __floats2half2_rn(v.x, v.y);
        __half2 h23 = __floats2half2_rn(v.z, v.w);
        float2  r01 = __half22float2(h01);
        float2  r23 = __half22float2(h23);
        __half2 l01 = __floats2half2_rn(v.x - r01.x, v.y - r01.y);
        __half2 l23 = __floats2half2_rn(v.z - r23.x, v.w - r23.y);
        const int off = row * LDA + c4 * 4;
        *(uint2*)&Ahi[off] = make_uint2(h2u(h01), h2u(h23));
        *(uint2*)&Alo[off] = make_uint2(h2u(l01), h2u(l23));
    }
    // ---- stage B (coalesced) ----
    #pragma unroll
    for (int i = 0; i < 8; i++) {
        const int f  = i * 256 + tid;    // float4 index in 128x64
        const int k  = f >> 4;           // 16 float4 per row
        const int c4 = f & 15;
        float4 v = *(const float4*)(W + (size_t)k * OUT_C + c4 * 4);
        __half2 h01 = __floats2half2_rn(v.x, v.y);
        __half2 h23 = __floats2half2_rn(v.z, v.w);
        float2  r01 = __half22float2(h01);
        float2  r23 = __half22float2(h23);
        __half2 l01 = __floats2half2_rn(v.x - r01.x, v.y - r01.y);
        __half2 l23 = __floats2half2_rn(v.z - r23.x, v.w - r23.y);
        const int off = k * LDB + c4 * 4;
        *(uint2*)&Bhi[off] = make_uint2(h2u(h01), h2u(h23));
        *(uint2*)&Blo[off] = make_uint2(h2u(l01), h2u(l23));
    }
    __syncthreads();

    wmma::fragment<wmma::accumulator, 16, 16, 16, float> acc[4];
    #pragma unroll
    for (int n = 0; n < 4; n++) wmma::fill_fragment(acc[n], 0.0f);

    #pragma unroll
    for (int k = 0; k < 8; k++) {
        wmma::fragment<wmma::matrix_a, 16, 16, 16, __half, wmma::row_major> ahi, alo;
        wmma::load_matrix_sync(ahi, &Ahi[(wid * 16) * LDA + k * 16], LDA);
        wmma::load_matrix_sync(alo, &Alo[(wid * 16) * LDA + k * 16], LDA);
        #pragma unroll
        for (int n = 0; n < 4; n++) {
            wmma::fragment<wmma::matrix_b, 16, 16, 16, __half, wmma::row_major> bhi, blo;
            wmma::load_matrix_sync(bhi, &Bhi[(k * 16) * LDB + n * 16], LDB);
            wmma::load_matrix_sync(blo, &Blo[(k * 16) * LDB + n * 16], LDB);
            wmma::mma_sync(acc[n], ahi, bhi, acc[n]);
            wmma::mma_sync(acc[n], ahi, blo, acc[n]);
            wmma::mma_sync(acc[n], alo, bhi, acc[n]);
        }
    }

    __syncthreads();
    #pragma unroll
    for (int n = 0; n < 4; n++)
        wmma::store_matrix_sync(&Cs[(wid * 16) * LDC + n * 16], acc[n], LDC, wmma::mem_row_major);
    __syncthreads();

    if (tid < GR) {
        const int row = row0 + tid;
        if (row < N_NODES) {
            const float* c = &Cs[tid * LDC];
            float sa[NH] = {0, 0, 0, 0}, sb[NH] = {0, 0, 0, 0};
            #pragma unroll
            for (int j = 0; j < OUT_C; j++) {
                const float v = c[j];
                const int hh = j >> 4;
                sa[hh] = fmaf(v, __ldg(&a_src[j]), sa[hh]);
                sb[hh] = fmaf(v, __ldg(&a_dst[j]), sb[hh]);
            }
            *(float4*)&g_sa[(size_t)row * NH] = make_float4(sa[0], sa[1], sa[2], sa[3]);
            *(float4*)&g_sb[(size_t)row * NH] = make_float4(sb[0], sb[1], sb[2], sb[3]);

            uint4* wout = (uint4*)&g_Wh[(size_t)row * OUT_C];
            #pragma unroll
            for (int q = 0; q < 8; q++) {
                uint4 u;
                ((__half2*)&u)[0] = __floats2half2_rn(c[q * 8 + 0], c[q * 8 + 1]);
                ((__half2*)&u)[1] = __floats2half2_rn(c[q * 8 + 2], c[q * 8 + 3]);
                ((__half2*)&u)[2] = __floats2half2_rn(c[q * 8 + 4], c[q * 8 + 5]);
                ((__half2*)&u)[3] = __floats2half2_rn(c[q * 8 + 6], c[q * 8 + 7]);
                wout[q] = u;
            }
        }
    }
}

// ---------------- fused CSR build: zero+detect | hist | scan | scatter --------
__global__ __launch_bounds__(BT, 1)
void build_kernel(const void* __restrict__ ei_raw)
{
    __shared__ int wsum[32];
    const int tid  = threadIdx.x;
    const int gtid = blockIdx.x * BT + tid;
    const int nth  = gridDim.x * BT;
    const unsigned nb = gridDim.x;

    // P0: zero histogram + dtype detect
    if (gtid < N_NODES) g_cnt[gtid] = 0;
    if (blockIdx.x == 0 && tid < 32) {
        const long long* p = (const long long*)ei_raw;
        int ok = 1;
        #pragma unroll
        for (int j = 0; j < 8; j++) {
            long long v = p[tid * 8 + j];
            if (v < 0 || v >= N_NODES) ok = 0;
        }
        unsigned m = __ballot_sync(0xffffffffu, ok);
        if (tid == 0) g_is64 = (m == 0xffffffffu) ? 1 : 0;
    }
    grid_bar(0, nb);

    const int is64 = g_is64;

    // P1: in-degree histogram (grid-stride)
    for (int e = gtid; e < E_EDGES; e += nth) {
        int dst = is64 ? (int)__ldg(&((const long long*)ei_raw)[(size_t)E_EDGES + e])
                       : __ldg(&((const int*)ei_raw)[(size_t)E_EDGES + e]);
        dst = min(max(dst, 0), N_NODES - 1);
        atomicAdd(&g_cnt[dst], 1);
    }
    grid_bar(1, nb);

    // P2: per-block partial sums
    {
        int s = (gtid < N_NODES) ? g_cnt[gtid] : 0;
        #pragma unroll
        for (int d = 16; d > 0; d >>= 1) s += __shfl_xor_sync(0xffffffffu, s, d);
        if ((tid & 31) == 0) wsum[tid >> 5] = s;
        __syncthreads();
        if (tid < 32) {
            int t = wsum[tid];
            #pragma unroll
            for (int d = 16; d > 0; d >>= 1) t += __shfl_xor_sync(0xffffffffu, t, d);
            if (tid == 0) g_part[blockIdx.x] = t;
        }
    }
    grid_bar(2, nb);

    // P3: exclusive scan of NBLK partials (block 0, single warp)
    if (blockIdx.x == 0 && tid < 32) {
        int carry = 0;
        for (int base = 0; base < NBLK; base += 32) {
            const int i = base + tid;
            const int v = (i < NBLK) ? g_part[i] : 0;
            int x = v;
            #pragma unroll
            for (int d = 1; d < 32; d <<= 1) {
                int y = __shfl_up_sync(0xffffffffu, x, d);
                if (tid >= d) x += y;
            }
            if (i < NBLK) g_part[i] = carry + x - v;
            carry += __shfl_sync(0xffffffffu, x, 31);
        }
    }
    grid_bar(3, nb);

    // P4: block-local exclusive scan + block offset -> g_off / g_pos
    {
        const int v = (gtid < N_NODES) ? g_cnt[gtid] : 0;
        int x = v;
        #pragma unroll
        for (int d = 1; d < 32; d <<= 1) {
            int y = __shfl_up_sync(0xffffffffu, x, d);
            if ((tid & 31) >= d) x += y;
        }
        if ((tid & 31) == 31) wsum[tid >> 5] = x;
        __syncthreads();
        if (tid < 32) {
            int s2 = wsum[tid];
            #pragma unroll
            for (int d = 1; d < 32; d <<= 1) {
                int y = __shfl_up_sync(0xffffffffu, s2, d);
                if (tid >= d) s2 += y;
            }
            wsum[tid] = s2;
        }
        __syncthreads();
        const int bp = ((tid >> 5) > 0) ? wsum[(tid >> 5) - 1] : 0;
        if (gtid < N_NODES) {
            const int off = g_part[blockIdx.x] + bp + x - v;
            g_off[gtid] = off;
            g_pos[gtid] = off;
        }
    }
    grid_bar(4, nb);

    // P5: scatter srcs into dst-grouped order (grid-stride, bounds-guarded)
    for (int e = gtid; e < E_EDGES; e += nth) {
        int src, dst;
        if (is64) {
            src = (int)__ldg(&((const long long*)ei_raw)[e]);
            dst = (int)__ldg(&((const long long*)ei_raw)[(size_t)E_EDGES + e]);
        } else {
            src = __ldg(&((const int*)ei_raw)[e]);
            dst = __ldg(&((const int*)ei_raw)[(size_t)E_EDGES + e]);
        }
        src = min(max(src, 0), N_NODES - 1);
        dst = min(max(dst, 0), N_NODES - 1);
        const int pos = atomicAdd(&g_pos[dst], 1);
        if (pos >= 0 && pos < E_EDGES) g_srcs[pos] = src;
    }
}

// ---------------- aggregate: one warp per dst node, branchless MLP-8 ----------
__global__ __launch_bounds__(256)
void aggregate_kernel(float* __restrict__ out)
{
    const int warp = (blockIdx.x * 256 + threadIdx.x) >> 5;
    const int lane = threadIdx.x & 31;
    if (warp >= N_NODES) return;
    const int n   = warp;
    const int off = g_off[n];
    const int deg = g_cnt[n];

    const int hh1 = lane & 3;   // phase-1 head
    const int g1  = lane >> 2;  // phase-1 edge-in-group
    const int hh2 = lane >> 3;  // phase-2 head for cols {2*lane, 2*lane+1}
    const float sb1 = g_sb[(size_t)n * NH + hh1];

    float acc0 = 0.0f, acc1 = 0.0f;

    for (int base = 0; base < deg; base += 8) {
        const int cnt = min(8, deg - base);   // uniform across warp

        // phase 1: lanes (g1, hh1) compute attention for edges base..base+cnt-1
        const int eidx = off + base + ((g1 < cnt) ? g1 : cnt - 1);
        const int src1 = g_srcs[eidx];
        float e = g_sa[(size_t)src1 * NH + hh1] + sb1;
        e = (e >= 0.0f) ? e : ALPHA * e;
        float m = e;
        m = fmaxf(m, __shfl_xor_sync(0xffffffffu, m, 1));
        m = fmaxf(m, __shfl_xor_sync(0xffffffffu, m, 2));
        const float x = __expf(e - m);
        float s = x;
        s += __shfl_xor_sync(0xffffffffu, s, 1);
        s += __shfl_xor_sync(0xffffffffu, s, 2);
        const float att1 = x / s;

        // phase 2a: batch all 8 gathers (branchless -> 8 loads in flight)
        float    av[8];
        unsigned wv[8];
        #pragma unroll
        for (int g = 0; g < 8; g++) {
            av[g] = __shfl_sync(0xffffffffu, att1, (g << 2) | hh2);
            const int sc = __shfl_sync(0xffffffffu, src1, g << 2);
            wv[g] = *(const unsigned*)&g_Wh[(size_t)sc * OUT_C + 2 * lane];
        }
        // phase 2b: FMA with zero weight for padded slots
        #pragma unroll
        for (int g = 0; g < 8; g++) {
            const float a = (g < cnt) ? av[g] : 0.0f;
            const float2 f = __half22float2(*(const __half2*)&wv[g]);
            acc0 = fmaf(a, f.x, acc0);
            acc1 = fmaf(a, f.y, acc1);
        }
    }

    *(float2*)&out[(size_t)n * OUT_C + 2 * lane] =
        make_float2(fmaxf(acc0, 0.0f), fmaxf(acc1, 0.0f));
}

// ---------------- launch ----------------
extern "C" void kernel_launch(void* const* d_in, const int* in_sizes, int n_in,
                              void* d_out, int out_size)
{
    const float* h     = nullptr;
    const void*  ei    = nullptr;
    const float* W     = nullptr;
    const float* a_src = nullptr;
    const float* a_dst = nullptr;
    for (int i = 0; i < n_in; i++) {
        const int s = in_sizes[i];
        if      (s == N_NODES * IN_F)  h  = (const float*)d_in[i];
        else if (s == 2 * E_EDGES)     ei = d_in[i];
        else if (s == IN_F * OUT_C)    W  = (const float*)d_in[i];
        else if (s == OUT_C) {
            if (!a_src) a_src = (const float*)d_in[i];
            else        a_dst = (const float*)d_in[i];
        }
    }
    if (!h || !ei || !W || !a_src || !a_dst) {
        h     = (const float*)d_in[0];
        ei    = d_in[1];
        W     = (const float*)d_in[2];
        a_src = (const float*)d_in[3];
        a_dst = (const float*)d_in[4];
    }
    float* out = (float*)d_out;

    cudaFuncSetAttribute(gemm_kernel,
                         cudaFuncAttributeMaxDynamicSharedMemorySize,
                         GEMM_SMEM_BYTES);
    gemm_kernel<<<(N_NODES + GR - 1) / GR, 256, GEMM_SMEM_BYTES>>>(h, W, a_src, a_dst);

    build_kernel<<<NBLK, BT>>>(ei);

    const int nwarps_blocks = (N_NODES * 32 + 255) / 256;  // one warp per node
    aggregate_kernel<<<nwarps_blocks, 256>>>(out);
}